// round 11
// baseline (speedup 1.0000x reference)
#include <cuda_runtime.h>
#include <stdint.h>

// Problem constants
#define S_LEN   2048
#define PATCH   16
#define NWIN    2033            // S_LEN - PATCH + 1
#define ND      4
#define NCAND   (ND * NWIN)     // 8132
#define NB      32
#define NC      8
#define NROWS   (NB * NC)       // 256
#define SXX_CONST 2728.0f       // sum_{k=0}^{31} (k-15.5)^2
#define CONV_ELEMS ((size_t)NROWS * ND * S_LEN)

// Scratch (static device globals; allocation-free).
// +16 zero pad: .bss zero-init, never written -> invalid gathers read 0.0f.
__device__ float    g_conv[CONV_ELEMS + 16];
__device__ uint32_t g_src[(size_t)NROWS * NCAND];

#define PAD_BYTE_OFF ((uint32_t)(CONV_ELEMS * 4))

// affine bit-function f(s) = (s & a) ^ b, packed as a | (b<<1).
// fcomb(first, second) = second ∘ first.
__device__ __forceinline__ int fcomb(int f1, int f2) {
    int a1 = f1 & 1, b1 = (f1 >> 1) & 1;
    int a2 = f2 & 1, b2 = (f2 >> 1) & 1;
    return (a1 & a2) | ((((b1 & a2) ^ b2)) << 1);
}

// ============================ K_conv =====================================
// 2 rows per block (grid 128 = one wave). Half-block (256 thr) per row.
__global__ __launch_bounds__(512) void k_conv(
    const float* __restrict__ seasonal,
    const float* __restrict__ conv_w,
    const float* __restrict__ conv_b)
{
    __shared__ float xs[2][S_LEN];
    __shared__ float ws[64];
    __shared__ float wb[4];

    const int tid  = threadIdx.x;
    const int half = tid >> 8;
    const int htid = tid & 255;
    const int row  = blockIdx.x * 2 + half;
    const int b    = row >> 3;
    const int c    = row & 7;

    if (tid < 64) ws[tid] = conv_w[tid];
    if (tid < 4)  wb[tid] = conv_b[tid];
    for (int s = htid; s < S_LEN; s += 256)
        xs[half][s] = seasonal[((size_t)b * S_LEN + s) * NC + c];
    __syncthreads();

    const float* x = xs[half];
    float* grow = g_conv + (size_t)row * ND * S_LEN;
    #pragma unroll 4
    for (int u = 0; u < (ND * S_LEN) / 256; u++) {
        int idx = u * 256 + htid;
        int di  = idx >> 11;
        int t   = idx & (S_LEN - 1);
        int dil = 1 << di;
        float acc = wb[di];
        #pragma unroll
        for (int k = 0; k < PATCH; k++) {
            int j = t - (15 - k) * dil;
            float xv = (j >= 0) ? x[j] : 0.0f;
            acc = fmaf(ws[di * PATCH + k], xv, acc);
        }
        grow[idx] = acc;
    }
}

// ============================ K_scan =====================================
// 2 rows per block (grid 128). Half-block (256 thr, 8 warps) per row, CH=32.
#define CH 32
__global__ __launch_bounds__(512) void k_scan()
{
    __shared__ int warpf[2][8];
    __shared__ int warpc[2][9];

    const int tid  = threadIdx.x;
    const int half = tid >> 8;
    const int htid = tid & 255;
    const int lane = htid & 31;
    const int hwid = htid >> 5;            // 0..7
    const int row  = blockIdx.x * 2 + half;

    const float* crow = g_conv + (size_t)row * ND * S_LEN;
    const int base = htid * CH;

    // ---- can_merge bits: rolling window raw moments ----
    uint32_t cmask = 0;
    {
        int d1 = base / NWIN;
        int t1 = base - d1 * NWIN;
        bool need_init = true;
        float S1 = 0.f, S2 = 0.f, M = 0.f;
        const float* rowp = crow + d1 * S_LEN;
        #pragma unroll 1
        for (int q = 0; q < CH; q++) {
            int i = base + q;
            if (i >= NCAND - 1) break;
            if (t1 == NWIN - 1) {
                // cross-dilation pair: direct 32-element evaluation
                const float* w1 = crow + d1 * S_LEN + t1;
                const float* w2 = crow + (d1 + 1) * S_LEN;
                float s = 0.f, s2 = 0.f, sk = 0.f;
                #pragma unroll
                for (int k = 0; k < 16; k++) {
                    float y = w1[k];
                    s += y; s2 = fmaf(y, y, s2); sk = fmaf(y, (float)k, sk);
                }
                #pragma unroll
                for (int k = 0; k < 16; k++) {
                    float y = w2[k];
                    s += y; s2 = fmaf(y, y, s2); sk = fmaf(y, (float)(16 + k), sk);
                }
                float sxy = sk - 15.5f * s;
                float syy = s2 - s * s * (1.0f / 32.0f);
                float r2 = (sxy * sxy) / (SXX_CONST * syy);
                if (r2 >= 0.5f) cmask |= 1u << q;
                d1++; t1 = 0;
                rowp = crow + d1 * S_LEN;
                need_init = true;
                continue;
            }
            if (need_init) {
                S1 = 0.f; S2 = 0.f; M = 0.f;
                #pragma unroll
                for (int k = 0; k < 16; k++) {
                    float y = rowp[t1 + k];
                    S1 += y; S2 = fmaf(y, y, S2); M = fmaf(y, (float)k, M);
                }
                need_init = false;
            }
            float y0  = rowp[t1];
            float y16 = rowp[t1 + 16];
            float S1n = S1 - y0 + y16;
            float S2n = S2 - y0 * y0 + y16 * y16;
            float Mn  = M + 15.0f * y16 + y0 - S1;
            float sy  = S1 + S1n;
            float sy2 = S2 + S2n;
            float syk = M + Mn + 16.0f * S1n;
            float sxy = syk - 15.5f * sy;
            float syy = sy2 - sy * sy * (1.0f / 32.0f);
            float r2 = (sxy * sxy) / (SXX_CONST * syy);  // syy<=0 -> NaN -> false
            if (r2 >= 0.5f) cmask |= 1u << q;
            S1 = S1n; S2 = S2n; M = Mn;
            t1++;
        }
    }

    // ---- chunk function in closed form ----
    // all-ones -> identity (even # of NOTs); else a=0, b=parity of trailing-ones.
    int f;
    {
        uint32_t t = ~cmask;
        if (t == 0) f = 1;
        else {
            int hz = 31 - __clz(t);
            int L  = 31 - hz;
            f = (L & 1) << 1;
        }
    }

    // ---- two-level non-commutative scan (8 warps per half) ----
    int finc = f;
    #pragma unroll
    for (int off = 1; off < 32; off <<= 1) {
        int g = __shfl_up_sync(0xffffffffu, finc, off);
        if (lane >= off) finc = fcomb(g, finc);
    }
    if (lane == 31) warpf[half][hwid] = finc;
    __syncthreads();
    if (hwid == 0) {
        int wf = (lane < 8) ? warpf[half][lane] : 1;
        #pragma unroll
        for (int off = 1; off < 8; off <<= 1) {
            int g = __shfl_up_sync(0xffffffffu, wf, off);
            if (lane >= off) wf = fcomb(g, wf);
        }
        if (lane < 8) warpf[half][lane] = wf;
    }
    __syncthreads();
    int fex = __shfl_up_sync(0xffffffffu, finc, 1);
    if (lane == 0) fex = 1;
    if (hwid > 0) fex = fcomb(warpf[half][hwid - 1], fex);
    int s = (fex >> 1) & 1;

    // ---- emit merge/valid bits + counts ----
    uint32_t mbits = 0, vbits = 0;
    int cnt = 0;
    #pragma unroll
    for (int q = 0; q < CH; q++) {
        int i = base + q;
        if (i >= NCAND) break;
        int ci = (cmask >> q) & 1;
        int v  = s ^ 1;
        int mg = v & ci;
        mbits |= (uint32_t)mg << q;
        vbits |= (uint32_t)v  << q;
        cnt += v;
        s = mg;
    }

    // ---- two-level add scan ----
    int cinc = cnt;
    #pragma unroll
    for (int off = 1; off < 32; off <<= 1) {
        int g = __shfl_up_sync(0xffffffffu, cinc, off);
        if (lane >= off) cinc += g;
    }
    if (lane == 31) warpc[half][hwid] = cinc;
    __syncthreads();
    if (hwid == 0) {
        int wc = (lane < 8) ? warpc[half][lane] : 0;
        #pragma unroll
        for (int off = 1; off < 8; off <<= 1) {
            int g = __shfl_up_sync(0xffffffffu, wc, off);
            if (lane >= off) wc += g;
        }
        if (lane < 8) warpc[half][lane] = wc;
        if (lane == 7) warpc[half][8] = wc;
    }
    __syncthreads();
    int pos = __shfl_up_sync(0xffffffffu, cinc, 1);
    if (lane == 0) pos = 0;
    if (hwid > 0) pos += warpc[half][hwid - 1];

    // ---- compaction: packed gather codes (t:12 | d:2 | merged:1) ----
    uint32_t* srow = g_src + (size_t)row * NCAND;
    {
        int d1 = base / NWIN;
        int t1 = base - d1 * NWIN;
        #pragma unroll 1
        for (int q = 0; q < CH; q++) {
            int i = base + q;
            if (i >= NCAND) break;
            if ((vbits >> q) & 1) {
                uint32_t code = (uint32_t)t1 | ((uint32_t)d1 << 12)
                              | (((mbits >> q) & 1u) << 14);
                srow[pos++] = code;
            }
            if (++t1 == NWIN) { t1 = 0; d1++; }
        }
    }
    int V = warpc[half][8];
    for (int j = V + htid; j < NCAND; j += 256) srow[j] = 0xFFFFFFFFu;
}

// ============================ k_out ======================================
// out[b, n, k, c], c fastest. Block = 32 n. Lane = (k = lane>>1, chalf =
// lane&1) so each lane produces one 16B chunk -> conflict-free STS.128 into
// a contiguous 16KB smem tile, then ONE cp.async.bulk (TMA) store per block
// replaces 1024 STG.128s (12 cyc issue each -> the R8 bottleneck).
__global__ __launch_bounds__(256) void k_out(float* __restrict__ out)
{
    __shared__ __align__(128) float tile[32 * PATCH * NC];   // 16 KB
    __shared__ uint2 soff[8][32];      // (o1, o2 | mergeflag<<31)

    const int b   = blockIdx.y;
    const int n0  = blockIdx.x * 32;
    const int tid = threadIdx.x;

    // ---- stage codes -> absolute byte offsets ----
    {
        int cc = tid >> 5, nj = tid & 31;
        int n = n0 + nj;
        uint32_t cd = (n < NCAND)
                    ? __ldcs(&g_src[(size_t)(b * 8 + cc) * NCAND + n])
                    : 0xFFFFFFFFu;
        uint32_t o1, o2;
        if (cd == 0xFFFFFFFFu) {
            o1 = PAD_BYTE_OFF; o2 = PAD_BYTE_OFF;
        } else {
            int t1 = cd & 0xFFF;
            int d1 = (cd >> 12) & 3;
            uint32_t rbase = (uint32_t)((b * 8 + cc) * ND * S_LEN) * 4u;
            o1 = rbase + (uint32_t)(d1 * S_LEN + t1) * 4u;
            if (cd & (1u << 14)) {
                int t2 = t1 + 1, d2 = d1;
                if (t2 == NWIN) { t2 = 0; d2 = d1 + 1; }
                o2 = (rbase + (uint32_t)(d2 * S_LEN + t2) * 4u) | 0x80000000u;
            } else {
                o2 = o1;
            }
        }
        soff[cc][nj] = make_uint2(o1, o2);
    }
    __syncthreads();

    const int w    = tid >> 5;          // warp 0..7 -> n-group w*4..w*4+3
    const int lane = tid & 31;
    const int k    = lane >> 1;
    const int ch   = lane & 1;          // c-half: c = ch*4 .. ch*4+3
    const char* gp = (const char*)g_conv;
    const uint32_t k4 = (uint32_t)(k << 2);

    #pragma unroll
    for (int j = 0; j < 4; j++) {
        int nl = w * 4 + j;
        float v[4];
        #pragma unroll
        for (int ci = 0; ci < 4; ci++) {
            uint2 o = soff[ch * 4 + ci][nl];
            float v1 = __ldg((const float*)(gp + o.x + k4));
            float vv = v1;
            if (o.y & 0x80000000u) {
                float v2 = __ldg((const float*)(gp + (o.y & 0x7FFFFFFFu) + k4));
                vv = 0.5f * (v1 + v2);
            }
            v[ci] = vv;
        }
        // chunk = lane: words [nl*128 + lane*4, +4) -> (n=nl, k, c=ch*4..+3)
        *(float4*)(tile + nl * 128 + lane * 4) = make_float4(v[0], v[1], v[2], v[3]);
    }
    __syncthreads();

    if (tid == 0) {
        int nvalid = NCAND - n0; if (nvalid > 32) nvalid = 32;
        int bytes = nvalid * PATCH * NC * 4;
        float* gdst = out + ((size_t)b * NCAND + n0) * (PATCH * NC);
        uint32_t s_addr = (uint32_t)__cvta_generic_to_shared(tile);
        asm volatile("fence.proxy.async.shared::cta;" ::: "memory");
        asm volatile("cp.async.bulk.global.shared::cta.bulk_group [%0], [%1], %2;"
                     :: "l"(gdst), "r"(s_addr), "r"(bytes) : "memory");
        asm volatile("cp.async.bulk.commit_group;" ::: "memory");
        asm volatile("cp.async.bulk.wait_group 0;" ::: "memory");
    }
    __syncthreads();
}

extern "C" void kernel_launch(void* const* d_in, const int* in_sizes, int n_in,
                              void* d_out, int out_size)
{
    const float* seasonal = (const float*)d_in[0];
    const float* cw       = (const float*)d_in[1];
    const float* cb       = (const float*)d_in[2];
    float* out = (float*)d_out;

    k_conv<<<NROWS / 2, 512>>>(seasonal, cw, cb);
    k_scan<<<NROWS / 2, 512>>>();

    dim3 g((NCAND + 31) / 32, NB);
    k_out<<<g, 256>>>(out);
}

// round 12
// speedup vs baseline: 1.1053x; 1.1053x over previous
#include <cuda_runtime.h>
#include <stdint.h>

// Problem constants
#define S_LEN   2048
#define PATCH   16
#define NWIN    2033            // S_LEN - PATCH + 1
#define ND      4
#define NCAND   (ND * NWIN)     // 8132
#define NB      32
#define NC      8
#define NROWS   (NB * NC)       // 256
#define NT      512
#define NWARP   (NT / 32)       // 16
#define CH      16              // chunk per thread (NT*CH = 8192 >= NCAND)
#define SXX_CONST 2728.0f       // sum_{k=0}^{31} (k-15.5)^2
#define CONV_ELEMS ((size_t)NROWS * ND * S_LEN)

// Scratch (static device globals; allocation-free).
// +16 zero pad: .bss zero-init, never written -> invalid gathers read 0.0f.
__device__ float    g_conv[CONV_ELEMS + 16];
__device__ uint32_t g_src[(size_t)NROWS * NCAND];

#define PAD_BYTE_OFF ((uint32_t)(CONV_ELEMS * 4))

// affine bit-function f(s) = (s & a) ^ b, packed as a | (b<<1).
__device__ __forceinline__ int fcomb(int f1, int f2) {
    int a1 = f1 & 1, b1 = (f1 >> 1) & 1;
    int a2 = f2 & 1, b2 = (f2 >> 1) & 1;
    return (a1 & a2) | ((((b1 & a2) ^ b2)) << 1);
}

// ============================ K_conv (R8 version) ========================
__global__ __launch_bounds__(NT) void k_conv(
    const float* __restrict__ seasonal,
    const float* __restrict__ conv_w,
    const float* __restrict__ conv_b)
{
    __shared__ float xs[S_LEN];
    __shared__ float ws[64];
    __shared__ float wb[4];

    const int row = blockIdx.x;          // b*8 + c
    const int b   = row >> 3;
    const int c   = row & 7;
    const int tid = threadIdx.x;

    if (tid < 64) ws[tid] = conv_w[tid];
    if (tid < 4)  wb[tid] = conv_b[tid];
    for (int s = tid; s < S_LEN; s += NT)
        xs[s] = seasonal[((size_t)b * S_LEN + s) * NC + c];
    __syncthreads();

    float* grow = g_conv + (size_t)row * ND * S_LEN;
    #pragma unroll
    for (int u = 0; u < (ND * S_LEN) / NT; u++) {
        int idx = u * NT + tid;
        int di  = idx >> 11;
        int t   = idx & (S_LEN - 1);
        int dil = 1 << di;
        float acc = wb[di];
        #pragma unroll
        for (int k = 0; k < PATCH; k++) {
            int j = t - (15 - k) * dil;
            float xv = (j >= 0) ? xs[j] : 0.0f;
            acc = fmaf(ws[di * PATCH + k], xv, acc);
        }
        grow[idx] = acc;
    }
}

// ============================ K_scan (R8 version) ========================
__global__ __launch_bounds__(NT) void k_scan()
{
    __shared__ int warpf[NWARP];
    __shared__ int warpc[NWARP + 1];

    const int row  = blockIdx.x;
    const int tid  = threadIdx.x;
    const int lane = tid & 31;
    const int wid  = tid >> 5;

    const float* crow = g_conv + (size_t)row * ND * S_LEN;
    const int base = tid * CH;

    uint32_t cmask = 0;
    {
        int d1 = base / NWIN;
        int t1 = base - d1 * NWIN;
        bool need_init = true;
        float S1 = 0.f, S2 = 0.f, M = 0.f;
        const float* rowp = crow + d1 * S_LEN;
        #pragma unroll 1
        for (int q = 0; q < CH; q++) {
            int i = base + q;
            if (i >= NCAND - 1) break;
            if (t1 == NWIN - 1) {
                const float* w1 = crow + d1 * S_LEN + t1;
                const float* w2 = crow + (d1 + 1) * S_LEN;
                float s = 0.f, s2 = 0.f, sk = 0.f;
                #pragma unroll
                for (int k = 0; k < 16; k++) {
                    float y = w1[k];
                    s += y; s2 = fmaf(y, y, s2); sk = fmaf(y, (float)k, sk);
                }
                #pragma unroll
                for (int k = 0; k < 16; k++) {
                    float y = w2[k];
                    s += y; s2 = fmaf(y, y, s2); sk = fmaf(y, (float)(16 + k), sk);
                }
                float sxy = sk - 15.5f * s;
                float syy = s2 - s * s * (1.0f / 32.0f);
                float r2 = (sxy * sxy) / (SXX_CONST * syy);
                if (r2 >= 0.5f) cmask |= 1u << q;
                d1++; t1 = 0;
                rowp = crow + d1 * S_LEN;
                need_init = true;
                continue;
            }
            if (need_init) {
                S1 = 0.f; S2 = 0.f; M = 0.f;
                #pragma unroll
                for (int k = 0; k < 16; k++) {
                    float y = rowp[t1 + k];
                    S1 += y; S2 = fmaf(y, y, S2); M = fmaf(y, (float)k, M);
                }
                need_init = false;
            }
            float y0  = rowp[t1];
            float y16 = rowp[t1 + 16];
            float S1n = S1 - y0 + y16;
            float S2n = S2 - y0 * y0 + y16 * y16;
            float Mn  = M + 15.0f * y16 + y0 - S1;
            float sy  = S1 + S1n;
            float sy2 = S2 + S2n;
            float syk = M + Mn + 16.0f * S1n;
            float sxy = syk - 15.5f * sy;
            float syy = sy2 - sy * sy * (1.0f / 32.0f);
            float r2 = (sxy * sxy) / (SXX_CONST * syy);
            if (r2 >= 0.5f) cmask |= 1u << q;
            S1 = S1n; S2 = S2n; M = Mn;
            t1++;
        }
    }

    int f;
    {
        uint32_t t = (~cmask) & 0xFFFFu;
        if (t == 0) f = 1;
        else {
            int hz = 31 - __clz(t);
            int L  = 15 - hz;
            f = (L & 1) << 1;
        }
    }

    int finc = f;
    #pragma unroll
    for (int off = 1; off < 32; off <<= 1) {
        int g = __shfl_up_sync(0xffffffffu, finc, off);
        if (lane >= off) finc = fcomb(g, finc);
    }
    if (lane == 31) warpf[wid] = finc;
    __syncthreads();
    if (wid == 0) {
        int wf = (lane < NWARP) ? warpf[lane] : 1;
        #pragma unroll
        for (int off = 1; off < NWARP; off <<= 1) {
            int g = __shfl_up_sync(0xffffffffu, wf, off);
            if (lane >= off) wf = fcomb(g, wf);
        }
        if (lane < NWARP) warpf[lane] = wf;
    }
    __syncthreads();
    int fex = __shfl_up_sync(0xffffffffu, finc, 1);
    if (lane == 0) fex = 1;
    if (wid > 0)  fex = fcomb(warpf[wid - 1], fex);
    int s = (fex >> 1) & 1;

    uint32_t mbits = 0, vbits = 0;
    int cnt = 0;
    #pragma unroll
    for (int q = 0; q < CH; q++) {
        int i = base + q;
        if (i >= NCAND) break;
        int ci = (cmask >> q) & 1;
        int v  = s ^ 1;
        int mg = v & ci;
        mbits |= (uint32_t)mg << q;
        vbits |= (uint32_t)v  << q;
        cnt += v;
        s = mg;
    }

    int cinc = cnt;
    #pragma unroll
    for (int off = 1; off < 32; off <<= 1) {
        int g = __shfl_up_sync(0xffffffffu, cinc, off);
        if (lane >= off) cinc += g;
    }
    if (lane == 31) warpc[wid] = cinc;
    __syncthreads();
    if (wid == 0) {
        int wc = (lane < NWARP) ? warpc[lane] : 0;
        #pragma unroll
        for (int off = 1; off < NWARP; off <<= 1) {
            int g = __shfl_up_sync(0xffffffffu, wc, off);
            if (lane >= off) wc += g;
        }
        if (lane < NWARP) warpc[lane] = wc;
        if (lane == NWARP - 1) warpc[NWARP] = wc;
    }
    __syncthreads();
    int pos = __shfl_up_sync(0xffffffffu, cinc, 1);
    if (lane == 0) pos = 0;
    if (wid > 0) pos += warpc[wid - 1];

    uint32_t* srow = g_src + (size_t)row * NCAND;
    {
        int d1 = base / NWIN;
        int t1 = base - d1 * NWIN;
        #pragma unroll 1
        for (int q = 0; q < CH; q++) {
            int i = base + q;
            if (i >= NCAND) break;
            if ((vbits >> q) & 1) {
                uint32_t code = (uint32_t)t1 | ((uint32_t)d1 << 12)
                              | (((mbits >> q) & 1u) << 14);
                srow[pos++] = code;
            }
            if (++t1 == NWIN) { t1 = 0; d1++; }
        }
    }
    int V = warpc[NWARP];
    for (int j = V + tid; j < NCAND; j += NT) srow[j] = 0xFFFFFFFFu;
}

// ============================ k_out ======================================
// out[b, n, k, c], c fastest. Each block processes NTILE=5 tiles of 32 n.
// Per tile: stage per-(c,n) byte offsets, gather (same structure as the
// measured-45us STG version), write results with cheap STS.128 into a
// double-buffered 16KB smem tile, and stream it out with ONE pipelined
// cp.async.bulk per tile (wait_group 1 keeps one store in flight, so the
// TMA wait is off the critical path; only the final wait is exposed).
#define NTILE 5
__global__ __launch_bounds__(256) void k_out(float* __restrict__ out)
{
    __shared__ __align__(128) float tile[2][32 * PATCH * NC];   // 2 x 16 KB
    __shared__ uint2 soff[2][8][32];

    const int b    = blockIdx.y;
    const int tid  = threadIdx.x;
    const int k    = tid & 15;
    const int nl   = tid >> 4;          // 0..15
    const char* gp = (const char*)g_conv;
    const uint32_t k4 = (uint32_t)(k << 2);
    const int cc = tid >> 5, nj = tid & 31;

    #pragma unroll 1
    for (int tt = 0; tt < NTILE; tt++) {
        const int tileidx = blockIdx.x * NTILE + tt;
        const int n0 = tileidx * 32;
        const int buf = tt & 1;

        // free the buffer written 2 tiles ago (one store may stay in flight)
        if (tt >= 2 && tid == 0)
            asm volatile("cp.async.bulk.wait_group 1;" ::: "memory");

        // ---- stage codes -> absolute byte offsets ----
        {
            int n = n0 + nj;
            uint32_t cd = (n < NCAND)
                        ? __ldg(&g_src[(size_t)(b * 8 + cc) * NCAND + n])
                        : 0xFFFFFFFFu;
            uint32_t o1, o2;
            if (cd == 0xFFFFFFFFu) {
                o1 = PAD_BYTE_OFF; o2 = PAD_BYTE_OFF;
            } else {
                int t1 = cd & 0xFFF;
                int d1 = (cd >> 12) & 3;
                uint32_t rbase = (uint32_t)((b * 8 + cc) * ND * S_LEN) * 4u;
                o1 = rbase + (uint32_t)(d1 * S_LEN + t1) * 4u;
                if (cd & (1u << 14)) {
                    int t2 = t1 + 1, d2 = d1;
                    if (t2 == NWIN) { t2 = 0; d2 = d1 + 1; }
                    o2 = (rbase + (uint32_t)(d2 * S_LEN + t2) * 4u) | 0x80000000u;
                } else {
                    o2 = o1;
                }
            }
            soff[buf][cc][nj] = make_uint2(o1, o2);
        }
        __syncthreads();     // soff ready + buffer free for all threads

        // ---- gather two n per thread, STS.128 into the tile ----
        const int nlB = nl + 16;
        float bufA[8], bufB[8];
        #pragma unroll
        for (int c = 0; c < 8; c++) {
            uint2 oa = soff[buf][c][nl];
            uint2 ob = soff[buf][c][nlB];
            float va1 = __ldg((const float*)(gp + oa.x + k4));
            float vb1 = __ldg((const float*)(gp + ob.x + k4));
            float va = va1, vb = vb1;
            if (oa.y & 0x80000000u) {
                float va2 = __ldg((const float*)(gp + (oa.y & 0x7FFFFFFFu) + k4));
                va = 0.5f * (va1 + va2);
            }
            if (ob.y & 0x80000000u) {
                float vb2 = __ldg((const float*)(gp + (ob.y & 0x7FFFFFFFu) + k4));
                vb = 0.5f * (vb1 + vb2);
            }
            bufA[c] = va;
            bufB[c] = vb;
        }
        float* ta = tile[buf] + nl  * 128 + k * 8;
        float* tb = tile[buf] + nlB * 128 + k * 8;
        *(float4*)(ta)     = make_float4(bufA[0], bufA[1], bufA[2], bufA[3]);
        *(float4*)(ta + 4) = make_float4(bufA[4], bufA[5], bufA[6], bufA[7]);
        *(float4*)(tb)     = make_float4(bufB[0], bufB[1], bufB[2], bufB[3]);
        *(float4*)(tb + 4) = make_float4(bufB[4], bufB[5], bufB[6], bufB[7]);
        __syncthreads();

        // ---- one bulk store per tile (pipelined) ----
        if (tid == 0) {
            int nvalid = NCAND - n0; if (nvalid > 32) nvalid = 32;
            int bytes = nvalid * PATCH * NC * 4;
            float* gdst = out + ((size_t)b * NCAND + n0) * (PATCH * NC);
            uint32_t s_addr = (uint32_t)__cvta_generic_to_shared(tile[buf]);
            asm volatile("fence.proxy.async.shared::cta;" ::: "memory");
            asm volatile("cp.async.bulk.global.shared::cta.bulk_group [%0], [%1], %2;"
                         :: "l"(gdst), "r"(s_addr), "r"(bytes) : "memory");
            asm volatile("cp.async.bulk.commit_group;" ::: "memory");
        }
    }

    if (tid == 0)
        asm volatile("cp.async.bulk.wait_group 0;" ::: "memory");
    __syncthreads();
}

extern "C" void kernel_launch(void* const* d_in, const int* in_sizes, int n_in,
                              void* d_out, int out_size)
{
    const float* seasonal = (const float*)d_in[0];
    const float* cw       = (const float*)d_in[1];
    const float* cb       = (const float*)d_in[2];
    float* out = (float*)d_out;

    k_conv<<<NROWS, NT>>>(seasonal, cw, cb);
    k_scan<<<NROWS, NT>>>();

    // 255 tiles of 32 n per batch = 51 blocks x NTILE(5) tiles
    dim3 g(51, NB);
    k_out<<<g, 256>>>(out);
}